// round 17
// baseline (speedup 1.0000x reference)
#include <cuda_runtime.h>
#include <cuda_fp16.h>
#include <cstdint>

// GaussianMixture NLL: N=65536 samples (2D), M=1024 mixtures.  SPARSITY == 0.
// nll = -sum_n log( sum_m exp(wlog_m - qf(n,m)) )
//
// v16 (re-bench after infra failure): R15 tensor-core formulation
//  (mma.m16n8k8.f16 poly + ex2.f16x2 epilogue, hot kernel at the MUFU floor)
//  with TWO 64-sample groups per block: grid 1024 -> 512 to cut wave/launch
//  overhead (R14 evidence: grid=512 had 2.2us wall overhead vs 4.1us at 1024).

#define M_MIX   1024
#define TPB     256
#define GROUPS  2
#define SAMP_PER_BLK  128        // 2 groups * 64
#define BIAS    8.0f

#define PREP_BLOCKS  8
#define PREP_TPB     64

// per-mixture coefficient record in B-fragment order:
//   word0 = (c0,c1)  word1 = (c2,c3)  word2 = (c4,c5b)  word3 = (0,0)
__device__ uint4 g_params[M_MIX];

// ---------- helpers ----------
__device__ __forceinline__ __half2 u2h2(unsigned int u) {
    __half2 h; *(unsigned int*)&h = u; return h;
}
__device__ __forceinline__ unsigned int h2u(__half2 h) {
    return *(unsigned int*)&h;
}
__device__ __forceinline__ unsigned int hex2u(unsigned int x) {
    unsigned int y;
    asm("ex2.approx.f16x2 %0, %1;" : "=r"(y) : "r"(x));
    return y;
}
__device__ __forceinline__ unsigned int hadd2u(unsigned int a, unsigned int b) {
    unsigned int y;
    asm("add.rn.f16x2 %0, %1, %2;" : "=r"(y) : "r"(a), "r"(b));
    return y;
}
// m16n8k8 f16 MMA, C = 0
__device__ __forceinline__ void mma16n8k8(unsigned int& d0, unsigned int& d1,
                                          unsigned int a0, unsigned int a1,
                                          unsigned int b0) {
    unsigned int z = 0u;
    asm("mma.sync.aligned.m16n8k8.row.col.f16.f16.f16.f16 "
        "{%0,%1}, {%2,%3}, {%4}, {%5,%6};"
        : "=r"(d0), "=r"(d1)
        : "r"(a0), "r"(a1), "r"(b0), "r"(z), "r"(z));
}

// ---------- per-mixture coefficient computation ----------
__device__ __forceinline__ void mix_coeffs(int m, float logZ,
                                           const float* __restrict__ mu,
                                           const float* __restrict__ sigma_log,
                                           const float* __restrict__ theta,
                                           const float* __restrict__ w,
                                           float* C /*[6]*/) {
    const float wi  = w[m];
    const float sl0 = sigma_log[2 * m + 0];
    const float sl1 = sigma_log[2 * m + 1];
    const float a = __expf(-2.0f * sl0);
    const float b = __expf(-2.0f * sl1);
    float s, c;
    __sincosf(theta[m], &s, &c);

    const float g11 = a * c * c + b * s * s;
    const float g12 = (a - b) * c * s;
    const float g22 = a * s * s + b * c * c;
    const float wlog = wi - logZ - sl0 - sl1;

    const float mx = mu[2 * m + 0];
    const float my = mu[2 * m + 1];

    const float L2E = 1.4426950408889634f;
    const float qmu = g11 * mx * mx + 2.0f * g12 * mx * my + g22 * my * my;

    C[0] = -L2E * g11;
    C[1] = -L2E * 2.0f * g12;
    C[2] = -L2E * g22;
    C[3] =  L2E * 2.0f * (g11 * mx + g12 * my);
    C[4] =  L2E * 2.0f * (g12 * mx + g22 * my);
    C[5] =  L2E * (wlog - qmu) + BIAS;
}

// ---------- prep: 8 blocks, redundant per-block softmax, 1 thread = 2 mixtures ----------
__global__ void __launch_bounds__(PREP_TPB) gmm_prep(const float* __restrict__ mu,
                                                     const float* __restrict__ sigma_log,
                                                     const float* __restrict__ theta,
                                                     const float* __restrict__ w,
                                                     float* __restrict__ out) {
    __shared__ float red[2];
    const int tid  = threadIdx.x;            // 0..63
    const int lane = tid & 31;
    const int wrp  = tid >> 5;               // 0..1

    // each thread folds 16 of the 1024 w values
    float wv[16];
    float lmax = -1e30f;
    #pragma unroll
    for (int i = 0; i < 16; ++i) {
        wv[i] = w[tid + i * PREP_TPB];
        lmax = fmaxf(lmax, wv[i]);
    }
    #pragma unroll
    for (int o = 16; o > 0; o >>= 1) lmax = fmaxf(lmax, __shfl_xor_sync(~0u, lmax, o));
    if (lane == 0) red[wrp] = lmax;
    __syncthreads();
    const float wmax = fmaxf(red[0], red[1]);
    __syncthreads();

    float lsum = 0.0f;
    #pragma unroll
    for (int i = 0; i < 16; ++i) lsum += __expf(wv[i] - wmax);
    #pragma unroll
    for (int o = 16; o > 0; o >>= 1) lsum += __shfl_xor_sync(~0u, lsum, o);
    if (lane == 0) red[wrp] = lsum;
    __syncthreads();
    const float logZ = wmax + __logf(red[0] + red[1]);

    const int p  = blockIdx.x * PREP_TPB + tid;   // 0..511
    #pragma unroll
    for (int h = 0; h < 2; ++h) {
        const int m = 2 * p + h;
        float C[6];
        mix_coeffs(m, logZ, mu, sigma_log, theta, w, C);
        uint4 r;
        r.x = h2u(__floats2half2_rn(C[0], C[1]));
        r.y = h2u(__floats2half2_rn(C[2], C[3]));
        r.z = h2u(__floats2half2_rn(C[4], C[5]));
        r.w = 0u;
        g_params[m] = r;
    }

    if (blockIdx.x == 0 && tid == 0) out[0] = 0.0f;   // re-zeroed every replay
}

// ---------- hot loop: tensor-core poly + MUFU ex2 epilogue ----------
__global__ void __launch_bounds__(TPB, 3) gmm_main(const float* __restrict__ sample,
                                                   float* __restrict__ out,
                                                   int N) {
    __shared__ __align__(16) uint4 spB[M_MIX];          // 16 KB B records
    __shared__ __align__(16) uint4 smA[SAMP_PER_BLK];   // 2 KB A monomials
    __shared__ float partial[8][SAMP_PER_BLK];          // 4 KB
    __shared__ float warpsum[8];

    const int tid  = threadIdx.x;
    const int lane = tid & 31;
    const int wid  = tid >> 5;

    // cooperative B load
    #pragma unroll
    for (int i = tid; i < M_MIX; i += TPB) spB[i] = g_params[i];

    const int base = blockIdx.x * SAMP_PER_BLK;

    // stage A monomials: [xx,xy,yy,x,y,1,0,0] fp16 per sample
    if (tid < SAMP_PER_BLK) {
        const int idx = base + tid;
        float x = 0.0f, y = 0.0f;
        if (idx < N) {
            const float2 sv = ((const float2*)sample)[idx];
            x = sv.x; y = sv.y;
        }
        uint4 r;
        r.x = h2u(__floats2half2_rn(x * x, x * y));
        r.y = h2u(__floats2half2_rn(y * y, x));
        r.z = h2u(__floats2half2_rn(y, 1.0f));
        r.w = 0u;
        smA[tid] = r;
    }
    __syncthreads();

    const unsigned int* A32 = (const unsigned int*)smA;
    const unsigned int* B32 = (const unsigned int*)spB;
    const int bbase = wid * 512;             // this warp's 128 mixtures (16 tiles)

    for (int g = 0; g < GROUPS; ++g) {       // two 64-sample groups
        // A fragments: 4 sample-tiles of 16 rows; lane-linear, conflict-free
        unsigned int a0[4], a1[4];
        #pragma unroll
        for (int st = 0; st < 4; ++st) {
            a0[st] = A32[g * 256 + st * 64 + lane];
            a1[st] = A32[g * 256 + st * 64 + 32 + lane];
        }

        float accFA[4] = {0.f, 0.f, 0.f, 0.f};
        float accFB[4] = {0.f, 0.f, 0.f, 0.f};

        #pragma unroll
        for (int tc = 0; tc < 2; ++tc) {     // 2 chunks of 8 mixture-tiles
            unsigned int hA[4] = {0u, 0u, 0u, 0u};
            unsigned int hB[4] = {0u, 0u, 0u, 0u};

            #pragma unroll
            for (int tt = 0; tt < 8; ++tt) {
                const unsigned int b = B32[bbase + (tc * 8 + tt) * 32 + lane];
                #pragma unroll
                for (int st = 0; st < 4; ++st) {
                    unsigned int d0, d1;
                    mma16n8k8(d0, d1, a0[st], a1[st], b);   // poly tile, log2-biased
                    hA[st] = hadd2u(hA[st], hex2u(d0));
                    hB[st] = hadd2u(hB[st], hex2u(d1));
                }
            }

            #pragma unroll
            for (int st = 0; st < 4; ++st) { // flush fp16 chunk to fp32
                const float2 fa = __half22float2(u2h2(hA[st]));
                const float2 fb = __half22float2(u2h2(hB[st]));
                accFA[st] += fa.x + fa.y;
                accFB[st] += fb.x + fb.y;
            }
        }

        // reduce cols within each 4-lane row group
        #pragma unroll
        for (int st = 0; st < 4; ++st) {
            float vA = accFA[st], vB = accFB[st];
            vA += __shfl_xor_sync(~0u, vA, 1);
            vA += __shfl_xor_sync(~0u, vA, 2);
            vB += __shfl_xor_sync(~0u, vB, 1);
            vB += __shfl_xor_sync(~0u, vB, 2);
            if ((lane & 3) == 0) {
                const int r = lane >> 2;
                partial[wid][g * 64 + st * 16 + r]     = vA;
                partial[wid][g * 64 + st * 16 + 8 + r] = vB;
            }
        }
    }
    __syncthreads();

    // combine warps; one sample per thread (tid < 128)
    float nll_i = 0.0f;
    if (tid < SAMP_PER_BLK) {
        const int sidx = base + tid;
        if (sidx < N) {
            float tot = 0.0f;
            #pragma unroll
            for (int q = 0; q < 8; ++q) tot += partial[q][tid];
            // tot = 2^BIAS * true_sum
            nll_i = 0.69314718055994531f * (BIAS - __log2f(tot));
        }
    }

    // block reduce
    #pragma unroll
    for (int o = 16; o > 0; o >>= 1)
        nll_i += __shfl_xor_sync(0xffffffffu, nll_i, o);
    if (lane == 0) warpsum[wid] = nll_i;
    __syncthreads();

    if (tid == 0) {
        float v = 0.0f;
        #pragma unroll
        for (int i = 0; i < 8; ++i) v += warpsum[i];
        atomicAdd(out, v);
    }
}

extern "C" void kernel_launch(void* const* d_in, const int* in_sizes, int n_in,
                              void* d_out, int out_size) {
    const float* sample    = (const float*)d_in[0];
    const float* mu        = (const float*)d_in[1];
    const float* sigma_log = (const float*)d_in[2];
    const float* theta     = (const float*)d_in[3];
    const float* w         = (const float*)d_in[4];
    float* out = (float*)d_out;

    const int N = in_sizes[0] / 2;
    const int grid = (N + SAMP_PER_BLK - 1) / SAMP_PER_BLK;

    gmm_prep<<<PREP_BLOCKS, PREP_TPB>>>(mu, sigma_log, theta, w, out);
    gmm_main<<<grid, TPB>>>(sample, out, N);
}